// round 3
// baseline (speedup 1.0000x reference)
#include <cuda_runtime.h>
#include <cuda_bf16.h>
#include <cstdint>
#include <cstddef>

// ---------------------------------------------------------------------------
// Problem constants
// ---------------------------------------------------------------------------
static constexpr int MDIM = 8192;
static constexpr int NDIM = 4096;
static constexpr int KDIM = 4096;

static constexpr int MT = 128;      // CTA M tile
static constexpr int NT = 128;      // CTA N tile
static constexpr int KT = 128;      // K (int8 bytes) per pipeline stage
static constexpr int KB = KDIM / KT;          // 32 K-iterations
static constexpr int NSTAGE = 4;

static constexpr int A_TILE_BYTES = MT * KT;              // 16384
static constexpr int W_TILE_BYTES = NT * KT;              // 16384
static constexpr int STAGE_BYTES  = 2 * A_TILE_BYTES + W_TILE_BYTES; // 49152

static constexpr int SMEM_TOTAL = 1024 + NSTAGE * STAGE_BYTES;  // 197632

// ---------------------------------------------------------------------------
// Scratch: pre-swizzled (SW128) SMEM-ready tile blocks, int8.
//   A planes: [mb(64)][kb(32)] blocks of 128 rows x 128B, 16KB each
//   W:        [nb(32)][kb(32)] blocks of 128 rows x 128B, 16KB each
// ---------------------------------------------------------------------------
__device__ __align__(1024) unsigned char g_A1[(size_t)MDIM * KDIM];
__device__ __align__(1024) unsigned char g_A2[(size_t)MDIM * KDIM];
__device__ __align__(1024) unsigned char g_Wq[(size_t)NDIM * KDIM];
__device__ float g_rowsum[MDIM];
__device__ float g_rscale[MDIM];   // s1 per row; s2 = s1/252

// ---------------------------------------------------------------------------
// PTX helpers (base PTX only — nothing 'a'-gated)
// ---------------------------------------------------------------------------
__device__ __forceinline__ uint32_t smem_u32(const void* p) {
    uint32_t a;
    asm("{ .reg .u64 t; cvta.to.shared.u64 t, %1; cvt.u32.u64 %0, t; }"
        : "=r"(a) : "l"(p));
    return a;
}

__device__ __forceinline__ uint32_t swz(uint32_t b) {
    return b ^ ((b >> 3) & 0x70);
}

__device__ __forceinline__ void mbar_init(uint32_t mbar, uint32_t cnt) {
    asm volatile("mbarrier.init.shared.b64 [%0], %1;" :: "r"(mbar), "r"(cnt) : "memory");
}

__device__ __forceinline__ void mbar_arrive(uint32_t mbar) {
    asm volatile("mbarrier.arrive.shared.b64 _, [%0];" :: "r"(mbar) : "memory");
}

__device__ __forceinline__ void mbar_expect_tx(uint32_t mbar, uint32_t bytes) {
    asm volatile("mbarrier.arrive.expect_tx.shared.b64 _, [%0], %1;"
                 :: "r"(mbar), "r"(bytes) : "memory");
}

__device__ __forceinline__ void bar_wait(uint32_t mbar, uint32_t parity) {
    uint32_t done;
    asm volatile("{\n .reg .pred p;\n"
                 " mbarrier.try_wait.parity.acquire.cta.shared::cta.b64 p, [%1], %2;\n"
                 " selp.b32 %0, 1, 0, p;\n}"
                 : "=r"(done) : "r"(mbar), "r"(parity) : "memory");
    while (!done) {
        asm volatile("{\n .reg .pred p;\n"
                     " mbarrier.try_wait.parity.acquire.cta.shared::cta.b64 p, [%1], %2, 0x989680;\n"
                     " selp.b32 %0, 1, 0, p;\n}"
                     : "=r"(done) : "r"(mbar), "r"(parity) : "memory");
    }
}

__device__ __forceinline__ void bulk_g2s(uint32_t dst_smem, const void* src,
                                         uint32_t bytes, uint32_t mbar) {
    asm volatile(
        "cp.async.bulk.shared::cluster.global.mbarrier::complete_tx::bytes "
        "[%0], [%1], %2, [%3];"
        :: "r"(dst_smem), "l"(src), "r"(bytes), "r"(mbar) : "memory");
}

__device__ __forceinline__ void ldsm_x4(uint32_t& r0, uint32_t& r1,
                                        uint32_t& r2, uint32_t& r3, uint32_t addr) {
    asm volatile("ldmatrix.sync.aligned.m8n8.x4.shared.b16 {%0,%1,%2,%3}, [%4];"
                 : "=r"(r0), "=r"(r1), "=r"(r2), "=r"(r3) : "r"(addr));
}

__device__ __forceinline__ void mma_s8(int* c, uint32_t a0, uint32_t a1,
                                       uint32_t a2, uint32_t a3,
                                       uint32_t b0, uint32_t b1) {
    asm volatile("mma.sync.aligned.m16n8k32.row.col.s32.s8.s8.s32 "
                 "{%0,%1,%2,%3}, {%4,%5,%6,%7}, {%8,%9}, {%0,%1,%2,%3};"
                 : "+r"(c[0]), "+r"(c[1]), "+r"(c[2]), "+r"(c[3])
                 : "r"(a0), "r"(a1), "r"(a2), "r"(a3), "r"(b0), "r"(b1));
}

// ---------------------------------------------------------------------------
// Prep 1: weight int32 (0..15) -> int8, SW128 tile blocks. 16 elems/thread.
// ---------------------------------------------------------------------------
__global__ void wconv_kernel(const int* __restrict__ q) {
    int idx = blockIdx.x * blockDim.x + threadIdx.x;
    if (idx >= NDIM * KDIM / 16) return;
    int n  = idx >> 8;              // 256 groups of 16 per row
    int k0 = (idx & 255) << 4;

    const int4* p = reinterpret_cast<const int4*>(q + (size_t)n * KDIM + k0);
    uint32_t w[4];
    #pragma unroll
    for (int i = 0; i < 4; i++) {
        int4 a = p[i];   // each component 0..15
        w[i] = (uint32_t)a.x | ((uint32_t)a.y << 8) |
               ((uint32_t)a.z << 16) | ((uint32_t)a.w << 24);
    }

    int nb = n >> 7;
    int r  = n & 127;
    int kb = k0 >> 7;
    int c0 = k0 & 127;
    size_t off = ((size_t)(nb * KB + kb)) * W_TILE_BYTES
               + swz((uint32_t)(r * 128 + c0));
    *reinterpret_cast<uint4*>(g_Wq + off) = make_uint4(w[0], w[1], w[2], w[3]);
}

// ---------------------------------------------------------------------------
// Prep 2: x fp32 -> two int8 residual planes (per-row scales) + rowsum.
// One block (256 threads) per row; 16 elements per thread held in registers.
// ---------------------------------------------------------------------------
__global__ void xconv_kernel(const float* __restrict__ x) {
    const int m = blockIdx.x;
    const int t = threadIdx.x;
    const float4* row = reinterpret_cast<const float4*>(x + (size_t)m * KDIM);

    float4 v[4];
    float amax = 0.f, sum = 0.f;
    #pragma unroll
    for (int i = 0; i < 4; i++) {
        v[i] = row[t + i * 256];
        amax = fmaxf(amax, fmaxf(fmaxf(fabsf(v[i].x), fabsf(v[i].y)),
                                 fmaxf(fabsf(v[i].z), fabsf(v[i].w))));
        sum += (v[i].x + v[i].y) + (v[i].z + v[i].w);
    }

    #pragma unroll
    for (int o = 16; o; o >>= 1) {
        amax = fmaxf(amax, __shfl_xor_sync(0xFFFFFFFFu, amax, o));
        sum += __shfl_xor_sync(0xFFFFFFFFu, sum, o);
    }
    __shared__ float sMax[8], sSum[8], sB[2];
    if ((t & 31) == 0) { sMax[t >> 5] = amax; sSum[t >> 5] = sum; }
    __syncthreads();
    if (t == 0) {
        float ma = 0.f, su = 0.f;
        #pragma unroll
        for (int i = 0; i < 8; i++) { ma = fmaxf(ma, sMax[i]); su += sSum[i]; }
        ma = fmaxf(ma, 1e-30f);
        sB[0] = ma;
        sB[1] = su;
        g_rowsum[m] = su;
        g_rscale[m] = ma / 127.0f;
    }
    __syncthreads();
    const float s1   = sB[0] / 127.0f;
    const float inv1 = 127.0f / sB[0];
    const float inv2 = 252.0f / s1;     // s2 = s1/252, |p2| <= ~126

    const int mbB = m >> 7;
    const int r   = m & 127;
    const size_t abase = (size_t)mbB * ((size_t)KB * A_TILE_BYTES);

    #pragma unroll
    for (int i = 0; i < 4; i++) {
        int p1x = __float2int_rn(v[i].x * inv1);
        int p1y = __float2int_rn(v[i].y * inv1);
        int p1z = __float2int_rn(v[i].z * inv1);
        int p1w = __float2int_rn(v[i].w * inv1);
        float rx = fmaf(-s1, (float)p1x, v[i].x);
        float ry = fmaf(-s1, (float)p1y, v[i].y);
        float rz = fmaf(-s1, (float)p1z, v[i].z);
        float rw = fmaf(-s1, (float)p1w, v[i].w);
        int p2x = __float2int_rn(rx * inv2);
        int p2y = __float2int_rn(ry * inv2);
        int p2z = __float2int_rn(rz * inv2);
        int p2w = __float2int_rn(rw * inv2);

        uint32_t a1 = (uint32_t)(uint8_t)p1x | ((uint32_t)(uint8_t)p1y << 8) |
                      ((uint32_t)(uint8_t)p1z << 16) | ((uint32_t)(uint8_t)p1w << 24);
        uint32_t a2 = (uint32_t)(uint8_t)p2x | ((uint32_t)(uint8_t)p2y << 8) |
                      ((uint32_t)(uint8_t)p2z << 16) | ((uint32_t)(uint8_t)p2w << 24);

        int g  = t + i * 256;
        int k0 = g << 2;
        int kb = k0 >> 7;
        int c0 = k0 & 127;
        size_t off = abase + (size_t)kb * A_TILE_BYTES
                   + swz((uint32_t)(r * 128 + c0));
        *reinterpret_cast<uint32_t*>(g_A1 + off) = a1;
        *reinterpret_cast<uint32_t*>(g_A2 + off) = a2;
    }
}

// ---------------------------------------------------------------------------
// GEMM: 128x128 CTA tile, 8 compute warps (each 32x64) + 1 producer warp.
// cp.async.bulk 4-stage pipeline; ldmatrix + mma.sync.m16n8k32.s8;
// two int8 planes into two exact s32 accumulator sets.
// ---------------------------------------------------------------------------
__global__ void __launch_bounds__(288, 1)
qgemm_kernel(const float* __restrict__ scale_p,
             const float* __restrict__ zp_p,
             const float* __restrict__ bias,
             float* __restrict__ out)
{
    extern __shared__ __align__(1024) unsigned char smem[];
    const uint32_t sb = smem_u32(smem);
    const int tid = threadIdx.x;
    const int wid = tid >> 5;            // 0..8
    const int lid = tid & 31;
    const int mb  = blockIdx.y;          // 0..63
    const int nb  = blockIdx.x;          // 0..31

    const uint32_t FULLB  = sb;          // 4 x 8B
    const uint32_t EMPTYB = sb + 64;     // 4 x 8B
    const uint32_t TILE0  = sb + 1024;

    if (tid == 0) {
        #pragma unroll
        for (int s = 0; s < NSTAGE; s++) {
            mbar_init(FULLB  + 8 * s, 1);
            mbar_init(EMPTYB + 8 * s, 8);
        }
        asm volatile("fence.proxy.async.shared::cta;" ::: "memory");
    }
    __syncthreads();

    if (wid < 8 && lid == 0) {
        #pragma unroll
        for (int s = 0; s < NSTAGE; s++) mbar_arrive(EMPTYB + 8 * s);
    }

    if (wid == 8) {
        // ------------------------- producer -------------------------
        if (lid == 0) {
            const unsigned char* a1B = g_A1 + (size_t)mb * ((size_t)KB * A_TILE_BYTES);
            const unsigned char* a2B = g_A2 + (size_t)mb * ((size_t)KB * A_TILE_BYTES);
            const unsigned char* wB  = g_Wq + (size_t)nb * ((size_t)KB * W_TILE_BYTES);
            int s = 0, ph = 0;
            for (int kb = 0; kb < KB; kb++) {
                bar_wait(EMPTYB + 8 * s, ph);
                mbar_expect_tx(FULLB + 8 * s, STAGE_BYTES);
                uint32_t d = TILE0 + s * STAGE_BYTES;
                bulk_g2s(d,                    a1B + (size_t)kb * A_TILE_BYTES,
                         A_TILE_BYTES, FULLB + 8 * s);
                bulk_g2s(d + A_TILE_BYTES,     a2B + (size_t)kb * A_TILE_BYTES,
                         A_TILE_BYTES, FULLB + 8 * s);
                bulk_g2s(d + 2 * A_TILE_BYTES, wB  + (size_t)kb * W_TILE_BYTES,
                         W_TILE_BYTES, FULLB + 8 * s);
                if (++s == NSTAGE) { s = 0; ph ^= 1; }
            }
        }
        return;
    }

    // ------------------------- compute warps -------------------------
    const int wm = wid & 3;          // 32-row M slice
    const int wn = wid >> 2;         // 64-col N slice
    const int g  = lid >> 3;
    const int lr = lid & 7;

    // A: (g&1)=row half, (g>>1)=16B col half
    uint32_t aRow[2], aXor[2];
    #pragma unroll
    for (int mt = 0; mt < 2; mt++) {
        int r = wm * 32 + mt * 16 + (g & 1) * 8 + lr;
        aRow[mt] = (uint32_t)(r * 128);
        aXor[mt] = (uint32_t)((r & 7) << 4);
    }
    // B: (g>>1)=row half, (g&1)=16B col half
    uint32_t bRow[4], bXor[4];
    #pragma unroll
    for (int bt = 0; bt < 4; bt++) {
        int r = wn * 64 + bt * 16 + (g >> 1) * 8 + lr;
        bRow[bt] = (uint32_t)(r * 128);
        bXor[bt] = (uint32_t)((r & 7) << 4);
    }
    const uint32_t aCol = (uint32_t)((g >> 1) * 16);
    const uint32_t bCol = (uint32_t)((g & 1) * 16);

    int acc1[2][8][4], acc2[2][8][4];
    #pragma unroll
    for (int mt = 0; mt < 2; mt++)
        #pragma unroll
        for (int nt = 0; nt < 8; nt++)
            #pragma unroll
            for (int j = 0; j < 4; j++) { acc1[mt][nt][j] = 0; acc2[mt][nt][j] = 0; }

    int s = 0, ph = 0;
    for (int kb = 0; kb < KB; kb++) {
        bar_wait(FULLB + 8 * s, ph);
        const uint32_t dA1 = TILE0 + s * STAGE_BYTES;
        const uint32_t dA2 = dA1 + A_TILE_BYTES;
        const uint32_t dW  = dA1 + 2 * A_TILE_BYTES;

        #pragma unroll
        for (int ks = 0; ks < 4; ks++) {
            const uint32_t kOff = (uint32_t)(ks * 32);
            uint32_t ah[2][4], al[2][4];
            #pragma unroll
            for (int mt = 0; mt < 2; mt++) {
                uint32_t off = aRow[mt] + ((kOff + aCol) ^ aXor[mt]);
                ldsm_x4(ah[mt][0], ah[mt][1], ah[mt][2], ah[mt][3], dA1 + off);
                ldsm_x4(al[mt][0], al[mt][1], al[mt][2], al[mt][3], dA2 + off);
            }
            #pragma unroll
            for (int bt = 0; bt < 4; bt++) {
                uint32_t b0, b1, b2, b3;
                uint32_t off = bRow[bt] + ((kOff + bCol) ^ bXor[bt]);
                ldsm_x4(b0, b1, b2, b3, dW + off);
                #pragma unroll
                for (int mt = 0; mt < 2; mt++) {
                    mma_s8(acc1[mt][2 * bt + 0], ah[mt][0], ah[mt][1], ah[mt][2], ah[mt][3], b0, b1);
                    mma_s8(acc1[mt][2 * bt + 1], ah[mt][0], ah[mt][1], ah[mt][2], ah[mt][3], b2, b3);
                    mma_s8(acc2[mt][2 * bt + 0], al[mt][0], al[mt][1], al[mt][2], al[mt][3], b0, b1);
                    mma_s8(acc2[mt][2 * bt + 1], al[mt][0], al[mt][1], al[mt][2], al[mt][3], b2, b3);
                }
            }
        }
        if (lid == 0) mbar_arrive(EMPTYB + 8 * s);
        if (++s == NSTAGE) { s = 0; ph ^= 1; }
    }

    // ------------------------- epilogue -------------------------
    const float scl = *scale_p;
    const float zp  = *zp_p;
    const int mRow0 = mb * MT + wm * 32;
    const int nCol0 = nb * NT + wn * 64;

    #pragma unroll
    for (int mt = 0; mt < 2; mt++) {
        const int r0 = mRow0 + mt * 16 + (lid >> 2);
        const int r1 = r0 + 8;
        const float s1_0 = g_rscale[r0], s1_1 = g_rscale[r1];
        const float c1_0 = scl * s1_0,  c1_1 = scl * s1_1;
        const float c2_0 = c1_0 * (1.0f / 252.0f), c2_1 = c1_1 * (1.0f / 252.0f);
        const float base0 = -scl * zp * g_rowsum[r0];
        const float base1 = -scl * zp * g_rowsum[r1];
        float* o0 = out + (size_t)r0 * NDIM;
        float* o1 = out + (size_t)r1 * NDIM;
        #pragma unroll
        for (int nt = 0; nt < 8; nt++) {
            const int c = nCol0 + nt * 8 + 2 * (lid & 3);
            const float2 bv = *reinterpret_cast<const float2*>(bias + c);
            float2 v0, v1;
            v0.x = fmaf(c1_0, (float)acc1[mt][nt][0],
                   fmaf(c2_0, (float)acc2[mt][nt][0], base0 + bv.x));
            v0.y = fmaf(c1_0, (float)acc1[mt][nt][1],
                   fmaf(c2_0, (float)acc2[mt][nt][1], base0 + bv.y));
            v1.x = fmaf(c1_1, (float)acc1[mt][nt][2],
                   fmaf(c2_1, (float)acc2[mt][nt][2], base1 + bv.x));
            v1.y = fmaf(c1_1, (float)acc1[mt][nt][3],
                   fmaf(c2_1, (float)acc2[mt][nt][3], base1 + bv.y));
            *reinterpret_cast<float2*>(o0 + c) = v0;
            *reinterpret_cast<float2*>(o1 + c) = v1;
        }
    }
}

// ---------------------------------------------------------------------------
// kernel_launch
// ---------------------------------------------------------------------------
extern "C" void kernel_launch(void* const* d_in, const int* in_sizes, int n_in,
                              void* d_out, int out_size)
{
    (void)in_sizes; (void)n_in; (void)out_size;
    const float* x     = (const float*)d_in[0];
    const int*   wq    = (const int*)  d_in[1];
    const float* scale = (const float*)d_in[2];
    const float* zp    = (const float*)d_in[3];
    const float* bias  = (const float*)d_in[4];
    float* out = (float*)d_out;

    wconv_kernel<<<(NDIM * KDIM / 16 + 255) / 256, 256>>>(wq);
    xconv_kernel<<<MDIM, 256>>>(x);

    cudaFuncSetAttribute(qgemm_kernel,
                         cudaFuncAttributeMaxDynamicSharedMemorySize, SMEM_TOTAL);
    dim3 grid(NDIM / NT, MDIM / MT);   // (32, 64)
    qgemm_kernel<<<grid, 288, SMEM_TOTAL>>>(scale, zp, bias, out);
}

// round 4
// speedup vs baseline: 3.2069x; 3.2069x over previous
#include <cuda_runtime.h>
#include <cuda_bf16.h>
#include <cstdint>
#include <cstddef>

// ---------------------------------------------------------------------------
// Problem constants (fixed shapes)
// ---------------------------------------------------------------------------
static constexpr int MDIM = 8192;   // B*S
static constexpr int NDIM = 4096;   // D_OUT
static constexpr int KDIM = 4096;   // D_IN

static constexpr int MT = 128;      // M tile per CTA
static constexpr int NT = 256;      // N tile per CTA
static constexpr int KT = 64;       // K per pipeline stage
static constexpr int KB = KDIM / KT;          // 64 K-iterations
static constexpr int NSTAGE = 3;

static constexpr int A_TILE_BYTES = MT * KT * 2;          // 16384
static constexpr int W_TILE_BYTES = NT * KT * 2;          // 32768
static constexpr int STAGE_BYTES  = 2 * A_TILE_BYTES + W_TILE_BYTES; // 65536

static constexpr int SMEM_TOTAL = 2048 + NSTAGE * STAGE_BYTES;  // 198656

// ---------------------------------------------------------------------------
// Scratch (device globals). Pre-swizzled (SW128) SMEM-ready tile blocks:
//   A: [mb(64)][kb(64)] blocks of 128 rows x 128B, 16KB each
//   W: [nbp(16)][kb(64)] blocks of 256 rows x 128B, 32KB each
// ---------------------------------------------------------------------------
__device__ __align__(1024) unsigned char g_Ahi[(size_t)MDIM * KDIM * 2];
__device__ __align__(1024) unsigned char g_Alo[(size_t)MDIM * KDIM * 2];
__device__ __align__(1024) unsigned char g_Wb [(size_t)NDIM * KDIM * 2];
__device__ float g_rowsum[MDIM];

// ---------------------------------------------------------------------------
// PTX helpers (base sm_90 PTX only — NOTHING 'a'-gated)
// ---------------------------------------------------------------------------
__device__ __forceinline__ uint32_t smem_u32(const void* p) {
    uint32_t a;
    asm("{ .reg .u64 t; cvta.to.shared.u64 t, %1; cvt.u32.u64 %0, t; }"
        : "=r"(a) : "l"(p));
    return a;
}

__device__ __forceinline__ uint32_t swz(uint32_t b) {
    return b ^ ((b >> 3) & 0x70);
}

__device__ __forceinline__ void mbar_init(uint32_t mbar, uint32_t cnt) {
    asm volatile("mbarrier.init.shared.b64 [%0], %1;" :: "r"(mbar), "r"(cnt) : "memory");
}

__device__ __forceinline__ void mbar_arrive(uint32_t mbar) {
    asm volatile("mbarrier.arrive.shared.b64 _, [%0];" :: "r"(mbar) : "memory");
}

__device__ __forceinline__ void mbar_expect_tx(uint32_t mbar, uint32_t bytes) {
    asm volatile("mbarrier.arrive.expect_tx.shared.b64 _, [%0], %1;"
                 :: "r"(mbar), "r"(bytes) : "memory");
}

__device__ __forceinline__ void bar_wait(uint32_t mbar, uint32_t parity) {
    uint32_t done;
    asm volatile("{\n .reg .pred p;\n"
                 " mbarrier.try_wait.parity.acquire.cta.shared::cta.b64 p, [%1], %2;\n"
                 " selp.b32 %0, 1, 0, p;\n}"
                 : "=r"(done) : "r"(mbar), "r"(parity) : "memory");
    while (!done) {
        asm volatile("{\n .reg .pred p;\n"
                     " mbarrier.try_wait.parity.acquire.cta.shared::cta.b64 p, [%1], %2, 0x989680;\n"
                     " selp.b32 %0, 1, 0, p;\n}"
                     : "=r"(done) : "r"(mbar), "r"(parity) : "memory");
    }
}

__device__ __forceinline__ void bulk_g2s(uint32_t dst_smem, const void* src,
                                         uint32_t bytes, uint32_t mbar) {
    asm volatile(
        "cp.async.bulk.shared::cluster.global.mbarrier::complete_tx::bytes "
        "[%0], [%1], %2, [%3];"
        :: "r"(dst_smem), "l"(src), "r"(bytes), "r"(mbar) : "memory");
}

__device__ __forceinline__ void ldsm_x4(uint32_t& r0, uint32_t& r1,
                                        uint32_t& r2, uint32_t& r3, uint32_t addr) {
    asm volatile("ldmatrix.sync.aligned.m8n8.x4.shared.b16 {%0,%1,%2,%3}, [%4];"
                 : "=r"(r0), "=r"(r1), "=r"(r2), "=r"(r3) : "r"(addr));
}

__device__ __forceinline__ void mma_bf16(float* c, uint32_t a0, uint32_t a1,
                                         uint32_t a2, uint32_t a3,
                                         uint32_t b0, uint32_t b1) {
    asm volatile("mma.sync.aligned.m16n8k16.row.col.f32.bf16.bf16.f32 "
                 "{%0,%1,%2,%3}, {%4,%5,%6,%7}, {%8,%9}, {%0,%1,%2,%3};"
                 : "+f"(c[0]), "+f"(c[1]), "+f"(c[2]), "+f"(c[3])
                 : "r"(a0), "r"(a1), "r"(a2), "r"(a3), "r"(b0), "r"(b1));
}

__device__ __forceinline__ uint32_t pack_bf16f(float lo, float hi) {
    __nv_bfloat162 t = __floats2bfloat162_rn(lo, hi);
    return *reinterpret_cast<uint32_t*>(&t);
}

__device__ __forceinline__ uint32_t pack_bf16(__nv_bfloat16 lo, __nv_bfloat16 hi) {
    __nv_bfloat162 t = __halves2bfloat162(lo, hi);
    return *reinterpret_cast<uint32_t*>(&t);
}

// ---------------------------------------------------------------------------
// Prep kernel 1: weight int32 -> bf16 (exact: q in 0..15), SW128 tile blocks
// ---------------------------------------------------------------------------
__global__ void wconv_kernel(const int* __restrict__ q) {
    int idx = blockIdx.x * blockDim.x + threadIdx.x;   // one thread = 8 elems
    if (idx >= NDIM * KDIM / 8) return;
    int n  = idx >> 9;
    int k0 = (idx & 511) << 3;

    const int4* p = reinterpret_cast<const int4*>(q + (size_t)n * KDIM + k0);
    int4 a = p[0], b = p[1];
    uint32_t w0 = pack_bf16f((float)a.x, (float)a.y);
    uint32_t w1 = pack_bf16f((float)a.z, (float)a.w);
    uint32_t w2 = pack_bf16f((float)b.x, (float)b.y);
    uint32_t w3 = pack_bf16f((float)b.z, (float)b.w);

    int nbp = n >> 8;
    int r   = n & 255;
    int kb  = k0 >> 6;
    int c0  = k0 & 63;
    size_t off = ((size_t)(nbp * KB + kb)) * W_TILE_BYTES
               + swz((uint32_t)(r * 128 + c0 * 2));
    *reinterpret_cast<uint4*>(g_Wb + off) = make_uint4(w0, w1, w2, w3);
}

// ---------------------------------------------------------------------------
// Prep kernel 2: x fp32 -> (hi, lo) bf16 planes (swizzled) + row sums
// ---------------------------------------------------------------------------
__global__ void xconv_kernel(const float* __restrict__ x) {
    const int m = blockIdx.x;
    const int t = threadIdx.x;    // 256 threads
    const float4* row = reinterpret_cast<const float4*>(x + (size_t)m * KDIM);
    const int mbb = m >> 7;
    const int r   = m & 127;
    const size_t abase = (size_t)mbb * ((size_t)KB * A_TILE_BYTES);

    float sum = 0.f;
    #pragma unroll
    for (int i = 0; i < 4; i++) {
        int g = t + i * 256;
        float4 v = row[g];
        sum += (v.x + v.y) + (v.z + v.w);

        __nv_bfloat16 h0 = __float2bfloat16_rn(v.x);
        __nv_bfloat16 h1 = __float2bfloat16_rn(v.y);
        __nv_bfloat16 h2 = __float2bfloat16_rn(v.z);
        __nv_bfloat16 h3 = __float2bfloat16_rn(v.w);
        __nv_bfloat16 l0 = __float2bfloat16_rn(v.x - __bfloat162float(h0));
        __nv_bfloat16 l1 = __float2bfloat16_rn(v.y - __bfloat162float(h1));
        __nv_bfloat16 l2 = __float2bfloat16_rn(v.z - __bfloat162float(h2));
        __nv_bfloat16 l3 = __float2bfloat16_rn(v.w - __bfloat162float(h3));

        int k0 = g << 2;
        int kb = k0 >> 6;
        int c0 = k0 & 63;
        size_t off = abase + (size_t)kb * A_TILE_BYTES
                   + swz((uint32_t)(r * 128 + c0 * 2));
        *reinterpret_cast<uint2*>(g_Ahi + off) =
            make_uint2(pack_bf16(h0, h1), pack_bf16(h2, h3));
        *reinterpret_cast<uint2*>(g_Alo + off) =
            make_uint2(pack_bf16(l0, l1), pack_bf16(l2, l3));
    }

    #pragma unroll
    for (int o = 16; o; o >>= 1) sum += __shfl_xor_sync(0xFFFFFFFFu, sum, o);
    __shared__ float ws[8];
    if ((t & 31) == 0) ws[t >> 5] = sum;
    __syncthreads();
    if (t == 0) {
        float s = 0.f;
        #pragma unroll
        for (int i = 0; i < 8; i++) s += ws[i];
        g_rowsum[m] = s;
    }
}

// ---------------------------------------------------------------------------
// GEMM: 128x256 CTA tile. 8 compute warps (each 32x128) + 1 producer warp.
// Inner loop restructured: per ks, load ALL B frags + A-hi frags, sweep 32
// independent hi MMAs, load A-lo, sweep 32 independent lo MMAs. No
// back-to-back RAW on accumulators.
// ---------------------------------------------------------------------------
__global__ void __launch_bounds__(288, 1)
qgemm_kernel(const float* __restrict__ scale_p,
             const float* __restrict__ zp_p,
             const float* __restrict__ bias,
             float* __restrict__ out)
{
    extern __shared__ __align__(1024) unsigned char smem[];
    const uint32_t sb = smem_u32(smem);
    const int tid = threadIdx.x;
    const int wid = tid >> 5;            // 0..8
    const int lid = tid & 31;
    const int mb  = blockIdx.y;          // 0..63
    const int nbp = blockIdx.x;          // 0..15

    const uint32_t FULLB  = sb;          // 3 x 8B
    const uint32_t EMPTYB = sb + 32;     // 3 x 8B
    const uint32_t TILE0  = (sb + 2047) & ~1023u;

    if (tid == 0) {
        #pragma unroll
        for (int s = 0; s < NSTAGE; s++) {
            mbar_init(FULLB  + 8 * s, 1);
            mbar_init(EMPTYB + 8 * s, 8);
        }
        asm volatile("fence.proxy.async.shared::cta;" ::: "memory");
    }
    __syncthreads();

    if (wid < 8 && lid == 0) {
        #pragma unroll
        for (int s = 0; s < NSTAGE; s++) mbar_arrive(EMPTYB + 8 * s);
    }

    if (wid == 8) {
        // ------------------------- producer -------------------------
        if (lid == 0) {
            const unsigned char* aB = g_Ahi + (size_t)mb  * ((size_t)KB * A_TILE_BYTES);
            const unsigned char* lB = g_Alo + (size_t)mb  * ((size_t)KB * A_TILE_BYTES);
            const unsigned char* wB = g_Wb  + (size_t)nbp * ((size_t)KB * W_TILE_BYTES);
            int s = 0, ph = 0;
            for (int kb = 0; kb < KB; kb++) {
                bar_wait(EMPTYB + 8 * s, ph);
                mbar_expect_tx(FULLB + 8 * s, STAGE_BYTES);
                uint32_t d = TILE0 + s * STAGE_BYTES;
                bulk_g2s(d,                    aB + (size_t)kb * A_TILE_BYTES,
                         A_TILE_BYTES, FULLB + 8 * s);
                bulk_g2s(d + A_TILE_BYTES,     lB + (size_t)kb * A_TILE_BYTES,
                         A_TILE_BYTES, FULLB + 8 * s);
                bulk_g2s(d + 2 * A_TILE_BYTES, wB + (size_t)kb * W_TILE_BYTES,
                         W_TILE_BYTES, FULLB + 8 * s);
                if (++s == NSTAGE) { s = 0; ph ^= 1; }
            }
        }
        return;
    }

    // ------------------------- compute warps -------------------------
    const int wm = wid & 3;          // M sub-tile (32 rows)
    const int wn = wid >> 2;         // N sub-tile (128 cols)
    const int g  = lid >> 3;         // ldmatrix lane group 0..3
    const int lr = lid & 7;

    uint32_t aRow[2], aXor[2];
    #pragma unroll
    for (int mt = 0; mt < 2; mt++) {
        int r = wm * 32 + mt * 16 + (g & 1) * 8 + lr;
        aRow[mt] = (uint32_t)(r * 128);
        aXor[mt] = (uint32_t)((r & 7) << 4);
    }
    uint32_t bRow[8], bXor[8];
    #pragma unroll
    for (int bt = 0; bt < 8; bt++) {
        int r = wn * 128 + bt * 16 + (g >> 1) * 8 + lr;
        bRow[bt] = (uint32_t)(r * 128);
        bXor[bt] = (uint32_t)((r & 7) << 4);
    }
    const uint32_t aCol = (uint32_t)((g >> 1) * 16);
    const uint32_t bCol = (uint32_t)((g & 1) * 16);

    float acc[2][16][4];
    #pragma unroll
    for (int mt = 0; mt < 2; mt++)
        #pragma unroll
        for (int nt = 0; nt < 16; nt++)
            #pragma unroll
            for (int j = 0; j < 4; j++) acc[mt][nt][j] = 0.f;

    int s = 0, ph = 0;
    for (int kb = 0; kb < KB; kb++) {
        bar_wait(FULLB + 8 * s, ph);
        const uint32_t dH = TILE0 + s * STAGE_BYTES;
        const uint32_t dL = dH + A_TILE_BYTES;
        const uint32_t dW = dH + 2 * A_TILE_BYTES;

        #pragma unroll
        for (int ks = 0; ks < 4; ks++) {
            const uint32_t kOff = (uint32_t)(ks * 32);

            // --- load ALL B fragments for this ks (8 x ldsm.x4 = 32 regs)
            uint32_t bf[8][4];
            #pragma unroll
            for (int bt = 0; bt < 8; bt++) {
                uint32_t off = bRow[bt] + ((kOff + bCol) ^ bXor[bt]);
                ldsm_x4(bf[bt][0], bf[bt][1], bf[bt][2], bf[bt][3], dW + off);
            }
            // --- A hi fragments
            uint32_t ah[2][4];
            #pragma unroll
            for (int mt = 0; mt < 2; mt++) {
                uint32_t off = aRow[mt] + ((kOff + aCol) ^ aXor[mt]);
                ldsm_x4(ah[mt][0], ah[mt][1], ah[mt][2], ah[mt][3], dH + off);
            }
            // --- hi sweep: 32 MMAs, all distinct accumulators
            #pragma unroll
            for (int bt = 0; bt < 8; bt++) {
                #pragma unroll
                for (int mt = 0; mt < 2; mt++) {
                    mma_bf16(acc[mt][2 * bt + 0], ah[mt][0], ah[mt][1], ah[mt][2], ah[mt][3],
                             bf[bt][0], bf[bt][1]);
                    mma_bf16(acc[mt][2 * bt + 1], ah[mt][0], ah[mt][1], ah[mt][2], ah[mt][3],
                             bf[bt][2], bf[bt][3]);
                }
            }
            // --- A lo fragments (reuse ah registers' lifetime ends above)
            uint32_t al[2][4];
            #pragma unroll
            for (int mt = 0; mt < 2; mt++) {
                uint32_t off = aRow[mt] + ((kOff + aCol) ^ aXor[mt]);
                ldsm_x4(al[mt][0], al[mt][1], al[mt][2], al[mt][3], dL + off);
            }
            // --- lo sweep: 32 MMAs, RAW distance to hi sweep = 32 MMAs
            #pragma unroll
            for (int bt = 0; bt < 8; bt++) {
                #pragma unroll
                for (int mt = 0; mt < 2; mt++) {
                    mma_bf16(acc[mt][2 * bt + 0], al[mt][0], al[mt][1], al[mt][2], al[mt][3],
                             bf[bt][0], bf[bt][1]);
                    mma_bf16(acc[mt][2 * bt + 1], al[mt][0], al[mt][1], al[mt][2], al[mt][3],
                             bf[bt][2], bf[bt][3]);
                }
            }
        }
        if (lid == 0) mbar_arrive(EMPTYB + 8 * s);
        if (++s == NSTAGE) { s = 0; ph ^= 1; }
    }

    // ------------------------- epilogue -------------------------
    const float scl = *scale_p;
    const float zp  = *zp_p;
    const int mRow0 = mb * MT + wm * 32;
    const int nCol0 = nbp * NT + wn * 128;

    #pragma unroll
    for (int mt = 0; mt < 2; mt++) {
        const int r0 = mRow0 + mt * 16 + (lid >> 2);
        const int r1 = r0 + 8;
        const float base0 = -scl * zp * g_rowsum[r0];
        const float base1 = -scl * zp * g_rowsum[r1];
        float* o0 = out + (size_t)r0 * NDIM;
        float* o1 = out + (size_t)r1 * NDIM;
        #pragma unroll
        for (int nt = 0; nt < 16; nt++) {
            const int c = nCol0 + nt * 8 + 2 * (lid & 3);
            const float2 bv = *reinterpret_cast<const float2*>(bias + c);
            float2 v0, v1;
            v0.x = fmaf(scl, acc[mt][nt][0], base0 + bv.x);
            v0.y = fmaf(scl, acc[mt][nt][1], base0 + bv.y);
            v1.x = fmaf(scl, acc[mt][nt][2], base1 + bv.x);
            v1.y = fmaf(scl, acc[mt][nt][3], base1 + bv.y);
            *reinterpret_cast<float2*>(o0 + c) = v0;
            *reinterpret_cast<float2*>(o1 + c) = v1;
        }
    }
}

// ---------------------------------------------------------------------------
// kernel_launch
// ---------------------------------------------------------------------------
extern "C" void kernel_launch(void* const* d_in, const int* in_sizes, int n_in,
                              void* d_out, int out_size)
{
    (void)in_sizes; (void)n_in; (void)out_size;
    const float* x     = (const float*)d_in[0];
    const int*   wq    = (const int*)  d_in[1];
    const float* scale = (const float*)d_in[2];
    const float* zp    = (const float*)d_in[3];
    const float* bias  = (const float*)d_in[4];
    float* out = (float*)d_out;

    wconv_kernel<<<(NDIM * KDIM / 8 + 255) / 256, 256>>>(wq);
    xconv_kernel<<<MDIM, 256>>>(x);

    cudaFuncSetAttribute(qgemm_kernel,
                         cudaFuncAttributeMaxDynamicSharedMemorySize, SMEM_TOTAL);
    dim3 grid(NDIM / NT, MDIM / MT);   // (16, 64)
    qgemm_kernel<<<grid, 288, SMEM_TOTAL>>>(scale, zp, bias, out);
}

// round 5
// speedup vs baseline: 6.5297x; 2.0361x over previous
#include <cuda_runtime.h>
#include <cuda_fp16.h>
#include <cstdint>
#include <cstddef>

// ---------------------------------------------------------------------------
// Problem constants (fixed shapes)
// ---------------------------------------------------------------------------
static constexpr int MDIM = 8192;   // B*S
static constexpr int NDIM = 4096;   // D_OUT
static constexpr int KDIM = 4096;   // D_IN

static constexpr int MT = 128;      // M tile per CTA
static constexpr int NT = 256;      // N tile per CTA
static constexpr int KT = 64;       // K per pipeline stage
static constexpr int KB = KDIM / KT;          // 64 K-iterations
static constexpr int NSTAGE = 4;

static constexpr int A_TILE_BYTES = MT * KT * 2;          // 16384
static constexpr int W_TILE_BYTES = NT * KT * 2;          // 32768
static constexpr int STAGE_BYTES  = A_TILE_BYTES + W_TILE_BYTES;  // 49152

static constexpr int SMEM_TOTAL = 2048 + NSTAGE * STAGE_BYTES;    // 198656

// ---------------------------------------------------------------------------
// Scratch (device globals). Pre-swizzled (SW128) SMEM-ready tile blocks:
//   A (x in fp16):      [mb(64)][kb(64)] blocks of 128 rows x 128B, 16KB each
//   W (q-8 in fp16):    [nbp(16)][kb(64)] blocks of 256 rows x 128B, 32KB each
// ---------------------------------------------------------------------------
__device__ __align__(1024) unsigned char g_Ah[(size_t)MDIM * KDIM * 2];
__device__ __align__(1024) unsigned char g_Wb[(size_t)NDIM * KDIM * 2];
__device__ float g_rowsum[MDIM];

// ---------------------------------------------------------------------------
// PTX helpers (base PTX only — nothing 'a'-gated)
// ---------------------------------------------------------------------------
__device__ __forceinline__ uint32_t smem_u32(const void* p) {
    uint32_t a;
    asm("{ .reg .u64 t; cvta.to.shared.u64 t, %1; cvt.u32.u64 %0, t; }"
        : "=r"(a) : "l"(p));
    return a;
}

__device__ __forceinline__ uint32_t swz(uint32_t b) {
    return b ^ ((b >> 3) & 0x70);
}

__device__ __forceinline__ void mbar_init(uint32_t mbar, uint32_t cnt) {
    asm volatile("mbarrier.init.shared.b64 [%0], %1;" :: "r"(mbar), "r"(cnt) : "memory");
}

__device__ __forceinline__ void mbar_arrive(uint32_t mbar) {
    asm volatile("mbarrier.arrive.shared.b64 _, [%0];" :: "r"(mbar) : "memory");
}

__device__ __forceinline__ void mbar_expect_tx(uint32_t mbar, uint32_t bytes) {
    asm volatile("mbarrier.arrive.expect_tx.shared.b64 _, [%0], %1;"
                 :: "r"(mbar), "r"(bytes) : "memory");
}

__device__ __forceinline__ void bar_wait(uint32_t mbar, uint32_t parity) {
    uint32_t done;
    asm volatile("{\n .reg .pred p;\n"
                 " mbarrier.try_wait.parity.acquire.cta.shared::cta.b64 p, [%1], %2;\n"
                 " selp.b32 %0, 1, 0, p;\n}"
                 : "=r"(done) : "r"(mbar), "r"(parity) : "memory");
    while (!done) {
        asm volatile("{\n .reg .pred p;\n"
                     " mbarrier.try_wait.parity.acquire.cta.shared::cta.b64 p, [%1], %2, 0x989680;\n"
                     " selp.b32 %0, 1, 0, p;\n}"
                     : "=r"(done) : "r"(mbar), "r"(parity) : "memory");
    }
}

__device__ __forceinline__ void bulk_g2s(uint32_t dst_smem, const void* src,
                                         uint32_t bytes, uint32_t mbar) {
    asm volatile(
        "cp.async.bulk.shared::cluster.global.mbarrier::complete_tx::bytes "
        "[%0], [%1], %2, [%3];"
        :: "r"(dst_smem), "l"(src), "r"(bytes), "r"(mbar) : "memory");
}

__device__ __forceinline__ void ldsm_x4(uint32_t& r0, uint32_t& r1,
                                        uint32_t& r2, uint32_t& r3, uint32_t addr) {
    asm volatile("ldmatrix.sync.aligned.m8n8.x4.shared.b16 {%0,%1,%2,%3}, [%4];"
                 : "=r"(r0), "=r"(r1), "=r"(r2), "=r"(r3) : "r"(addr));
}

__device__ __forceinline__ void mma_f16(float* c, uint32_t a0, uint32_t a1,
                                        uint32_t a2, uint32_t a3,
                                        uint32_t b0, uint32_t b1) {
    asm volatile("mma.sync.aligned.m16n8k16.row.col.f32.f16.f16.f32 "
                 "{%0,%1,%2,%3}, {%4,%5,%6,%7}, {%8,%9}, {%0,%1,%2,%3};"
                 : "+f"(c[0]), "+f"(c[1]), "+f"(c[2]), "+f"(c[3])
                 : "r"(a0), "r"(a1), "r"(a2), "r"(a3), "r"(b0), "r"(b1));
}

__device__ __forceinline__ uint32_t pack_h2f(float lo, float hi) {
    __half2 t = __floats2half2_rn(lo, hi);
    return *reinterpret_cast<uint32_t*>(&t);
}

// ---------------------------------------------------------------------------
// Prep 1: weight int32 (0..15) -> fp16 (q - 8, exact), SW128 tile blocks
// ---------------------------------------------------------------------------
__global__ void wconv_kernel(const int* __restrict__ q) {
    int idx = blockIdx.x * blockDim.x + threadIdx.x;   // one thread = 8 elems
    if (idx >= NDIM * KDIM / 8) return;
    int n  = idx >> 9;
    int k0 = (idx & 511) << 3;

    const int4* p = reinterpret_cast<const int4*>(q + (size_t)n * KDIM + k0);
    int4 a = p[0], b = p[1];
    uint32_t w0 = pack_h2f((float)(a.x - 8), (float)(a.y - 8));
    uint32_t w1 = pack_h2f((float)(a.z - 8), (float)(a.w - 8));
    uint32_t w2 = pack_h2f((float)(b.x - 8), (float)(b.y - 8));
    uint32_t w3 = pack_h2f((float)(b.z - 8), (float)(b.w - 8));

    int nbp = n >> 8;
    int r   = n & 255;
    int kb  = k0 >> 6;
    int c0  = k0 & 63;
    size_t off = ((size_t)(nbp * KB + kb)) * W_TILE_BYTES
               + swz((uint32_t)(r * 128 + c0 * 2));
    *reinterpret_cast<uint4*>(g_Wb + off) = make_uint4(w0, w1, w2, w3);
}

// ---------------------------------------------------------------------------
// Prep 2: x fp32 -> fp16 plane (swizzled) + exact fp32 row sums
// ---------------------------------------------------------------------------
__global__ void xconv_kernel(const float* __restrict__ x) {
    const int m = blockIdx.x;
    const int t = threadIdx.x;    // 256 threads
    const float4* row = reinterpret_cast<const float4*>(x + (size_t)m * KDIM);
    const int mbb = m >> 7;
    const int r   = m & 127;
    const size_t abase = (size_t)mbb * ((size_t)KB * A_TILE_BYTES);

    float sum = 0.f;
    #pragma unroll
    for (int i = 0; i < 4; i++) {
        int g = t + i * 256;
        float4 v = row[g];
        sum += (v.x + v.y) + (v.z + v.w);

        int k0 = g << 2;
        int kb = k0 >> 6;
        int c0 = k0 & 63;
        size_t off = abase + (size_t)kb * A_TILE_BYTES
                   + swz((uint32_t)(r * 128 + c0 * 2));
        *reinterpret_cast<uint2*>(g_Ah + off) =
            make_uint2(pack_h2f(v.x, v.y), pack_h2f(v.z, v.w));
    }

    #pragma unroll
    for (int o = 16; o; o >>= 1) sum += __shfl_xor_sync(0xFFFFFFFFu, sum, o);
    __shared__ float ws[8];
    if ((t & 31) == 0) ws[t >> 5] = sum;
    __syncthreads();
    if (t == 0) {
        float s = 0.f;
        #pragma unroll
        for (int i = 0; i < 8; i++) s += ws[i];
        g_rowsum[m] = s;
    }
}

// ---------------------------------------------------------------------------
// GEMM: 128x256 CTA tile. 8 compute warps (each 32x128) + 1 producer warp.
// Single fp16 plane; y = scl*G + scl*(8-zp)*rowsum + bias.
// ---------------------------------------------------------------------------
__global__ void __launch_bounds__(288, 1)
qgemm_kernel(const float* __restrict__ scale_p,
             const float* __restrict__ zp_p,
             const float* __restrict__ bias,
             float* __restrict__ out)
{
    extern __shared__ __align__(1024) unsigned char smem[];
    const uint32_t sb = smem_u32(smem);
    const int tid = threadIdx.x;
    const int wid = tid >> 5;            // 0..8
    const int lid = tid & 31;
    const int mb  = blockIdx.y;          // 0..63
    const int nbp = blockIdx.x;          // 0..15

    const uint32_t FULLB  = sb;          // 4 x 8B
    const uint32_t EMPTYB = sb + 64;     // 4 x 8B
    const uint32_t TILE0  = (sb + 2047) & ~1023u;

    if (tid == 0) {
        #pragma unroll
        for (int s = 0; s < NSTAGE; s++) {
            mbar_init(FULLB  + 8 * s, 1);
            mbar_init(EMPTYB + 8 * s, 8);
        }
        asm volatile("fence.proxy.async.shared::cta;" ::: "memory");
    }
    __syncthreads();

    if (wid < 8 && lid == 0) {
        #pragma unroll
        for (int s = 0; s < NSTAGE; s++) mbar_arrive(EMPTYB + 8 * s);
    }

    if (wid == 8) {
        // ------------------------- producer -------------------------
        if (lid == 0) {
            const unsigned char* aB = g_Ah + (size_t)mb  * ((size_t)KB * A_TILE_BYTES);
            const unsigned char* wB = g_Wb + (size_t)nbp * ((size_t)KB * W_TILE_BYTES);
            int s = 0, ph = 0;
            for (int kb = 0; kb < KB; kb++) {
                bar_wait(EMPTYB + 8 * s, ph);
                mbar_expect_tx(FULLB + 8 * s, STAGE_BYTES);
                uint32_t d = TILE0 + s * STAGE_BYTES;
                bulk_g2s(d,                aB + (size_t)kb * A_TILE_BYTES,
                         A_TILE_BYTES, FULLB + 8 * s);
                bulk_g2s(d + A_TILE_BYTES, wB + (size_t)kb * W_TILE_BYTES,
                         W_TILE_BYTES, FULLB + 8 * s);
                if (++s == NSTAGE) { s = 0; ph ^= 1; }
            }
        }
        return;
    }

    // ------------------------- compute warps -------------------------
    const int wm = wid & 3;          // M sub-tile (32 rows)
    const int wn = wid >> 2;         // N sub-tile (128 cols)
    const int g  = lid >> 3;         // ldmatrix lane group 0..3
    const int lr = lid & 7;

    uint32_t aRow[2], aXor[2];
    #pragma unroll
    for (int mt = 0; mt < 2; mt++) {
        int r = wm * 32 + mt * 16 + (g & 1) * 8 + lr;
        aRow[mt] = (uint32_t)(r * 128);
        aXor[mt] = (uint32_t)((r & 7) << 4);
    }
    uint32_t bRow[8], bXor[8];
    #pragma unroll
    for (int bt = 0; bt < 8; bt++) {
        int r = wn * 128 + bt * 16 + (g >> 1) * 8 + lr;
        bRow[bt] = (uint32_t)(r * 128);
        bXor[bt] = (uint32_t)((r & 7) << 4);
    }
    const uint32_t aCol = (uint32_t)((g >> 1) * 16);
    const uint32_t bCol = (uint32_t)((g & 1) * 16);

    float acc[2][16][4];
    #pragma unroll
    for (int mt = 0; mt < 2; mt++)
        #pragma unroll
        for (int nt = 0; nt < 16; nt++)
            #pragma unroll
            for (int j = 0; j < 4; j++) acc[mt][nt][j] = 0.f;

    int s = 0, ph = 0;
    for (int kb = 0; kb < KB; kb++) {
        bar_wait(FULLB + 8 * s, ph);
        const uint32_t dA = TILE0 + s * STAGE_BYTES;
        const uint32_t dW = dA + A_TILE_BYTES;

        #pragma unroll
        for (int ks = 0; ks < 4; ks++) {
            const uint32_t kOff = (uint32_t)(ks * 32);

            uint32_t bf[8][4];
            #pragma unroll
            for (int bt = 0; bt < 8; bt++) {
                uint32_t off = bRow[bt] + ((kOff + bCol) ^ bXor[bt]);
                ldsm_x4(bf[bt][0], bf[bt][1], bf[bt][2], bf[bt][3], dW + off);
            }
            uint32_t ah[2][4];
            #pragma unroll
            for (int mt = 0; mt < 2; mt++) {
                uint32_t off = aRow[mt] + ((kOff + aCol) ^ aXor[mt]);
                ldsm_x4(ah[mt][0], ah[mt][1], ah[mt][2], ah[mt][3], dA + off);
            }
            #pragma unroll
            for (int bt = 0; bt < 8; bt++) {
                #pragma unroll
                for (int mt = 0; mt < 2; mt++) {
                    mma_f16(acc[mt][2 * bt + 0], ah[mt][0], ah[mt][1], ah[mt][2], ah[mt][3],
                            bf[bt][0], bf[bt][1]);
                    mma_f16(acc[mt][2 * bt + 1], ah[mt][0], ah[mt][1], ah[mt][2], ah[mt][3],
                            bf[bt][2], bf[bt][3]);
                }
            }
        }
        if (lid == 0) mbar_arrive(EMPTYB + 8 * s);
        if (++s == NSTAGE) { s = 0; ph ^= 1; }
    }

    // ------------------------- epilogue -------------------------
    const float scl = *scale_p;
    const float zp  = *zp_p;
    const int mRow0 = mb * MT + wm * 32;
    const int nCol0 = nbp * NT + wn * 128;

    #pragma unroll
    for (int mt = 0; mt < 2; mt++) {
        const int r0 = mRow0 + mt * 16 + (lid >> 2);
        const int r1 = r0 + 8;
        const float base0 = scl * (8.0f - zp) * g_rowsum[r0];
        const float base1 = scl * (8.0f - zp) * g_rowsum[r1];
        float* o0 = out + (size_t)r0 * NDIM;
        float* o1 = out + (size_t)r1 * NDIM;
        #pragma unroll
        for (int nt = 0; nt < 16; nt++) {
            const int c = nCol0 + nt * 8 + 2 * (lid & 3);
            const float2 bv = *reinterpret_cast<const float2*>(bias + c);
            float2 v0, v1;
            v0.x = fmaf(scl, acc[mt][nt][0], base0 + bv.x);
            v0.y = fmaf(scl, acc[mt][nt][1], base0 + bv.y);
            v1.x = fmaf(scl, acc[mt][nt][2], base1 + bv.x);
            v1.y = fmaf(scl, acc[mt][nt][3], base1 + bv.y);
            *reinterpret_cast<float2*>(o0 + c) = v0;
            *reinterpret_cast<float2*>(o1 + c) = v1;
        }
    }
}

// ---------------------------------------------------------------------------
// kernel_launch
// ---------------------------------------------------------------------------
extern "C" void kernel_launch(void* const* d_in, const int* in_sizes, int n_in,
                              void* d_out, int out_size)
{
    (void)in_sizes; (void)n_in; (void)out_size;
    const float* x     = (const float*)d_in[0];
    const int*   wq    = (const int*)  d_in[1];
    const float* scale = (const float*)d_in[2];
    const float* zp    = (const float*)d_in[3];
    const float* bias  = (const float*)d_in[4];
    float* out = (float*)d_out;

    wconv_kernel<<<(NDIM * KDIM / 8 + 255) / 256, 256>>>(wq);
    xconv_kernel<<<MDIM, 256>>>(x);

    cudaFuncSetAttribute(qgemm_kernel,
                         cudaFuncAttributeMaxDynamicSharedMemorySize, SMEM_TOTAL);
    dim3 grid(NDIM / NT, MDIM / MT);   // (16, 64)
    qgemm_kernel<<<grid, 288, SMEM_TOTAL>>>(scale, zp, bias, out);
}